// round 1
// baseline (speedup 1.0000x reference)
#include <cuda_runtime.h>
#include <math.h>

#define B_SZ 2048
#define M_SZ 1024
#define D_SZ 64
#define KDIM 128   // 2*D_SZ

// ---------------- device scratch (no allocations allowed) ----------------
__device__ float  g_Xcat[B_SZ * KDIM];          // [b][k] : k<64 -> x^2, k>=64 -> x
__device__ float  g_Bmat[KDIM * M_SZ];          // [k][m] : k<64 -> 1/Sigma, k>=64 -> -2*mut/Sigma
__device__ float2 g_hl[M_SZ];                   // (.x = -0.5*sum(mut^2/Sig + log Sig), .y = Lam)
__device__ float  g_P[M_SZ * KDIM];             // [m][k] : k<64 -> K, k>=64 -> c = v - K*mut
__device__ float  g_W[B_SZ * M_SZ];             // weights
__device__ float  g_Tpart[8 * B_SZ * KDIM];     // per-mchunk partial [T1|T2]
__device__ float  g_npart[8 * B_SZ];            // per-mchunk partial norm

// ---------------- kernel 1: per-component parameter precompute ----------------
__global__ void precompute_params(const float* __restrict__ Mu0,
                                  const float* __restrict__ Mu1,
                                  const float* __restrict__ S0,
                                  const float* __restrict__ S1,
                                  const float* __restrict__ Lam,
                                  const float* __restrict__ tp,
                                  const float* __restrict__ ep) {
    int m = blockIdx.x;
    int d = threadIdx.x;      // 64 threads
    float t   = tp[0];
    float eps = ep[0];
    float eps2 = eps * eps;
    float eps4 = eps2 * eps2;
    float omt  = 1.0f - t;

    int id = m * D_SZ + d;
    float s0  = S0[id], s1 = S1[id];
    float mu0 = Mu0[id], mu1 = Mu1[id];

    float Ds = sqrtf(4.0f * s0 * s1 + eps4);
    float Cs = 0.5f * (Ds - eps2);
    float mt = omt * mu0 + t * mu1;
    float Sg = omt * omt * s0 + t * t * s1 + 2.0f * t * omt * (Cs + 0.5f * eps2);
    float Pt = t * s1 + omt * Cs;
    float Qt = omt * s0 + t * Cs;
    float St = Pt - Qt - eps2 * t;
    float inv = 1.0f / Sg;
    float Kk  = St * inv;
    float v   = mu1 - mu0;
    float c   = v - Kk * mt;

    g_Bmat[d * M_SZ + m]           = inv;
    g_Bmat[(D_SZ + d) * M_SZ + m]  = -2.0f * mt * inv;
    g_P[m * KDIM + d]              = Kk;
    g_P[m * KDIM + D_SZ + d]       = c;

    // reduce h = sum_d (mut^2*inv + log Sigma)
    __shared__ float red[64];
    red[d] = mt * mt * inv + logf(Sg);
    __syncthreads();
    #pragma unroll
    for (int s = 32; s > 0; s >>= 1) {
        if (d < s) red[d] += red[d + s];
        __syncthreads();
    }
    if (d == 0) g_hl[m] = make_float2(-0.5f * red[0], Lam[m]);
}

// ---------------- kernel 2: build Xcat ----------------
__global__ void precompute_x(const float* __restrict__ X) {
    int i = blockIdx.x * blockDim.x + threadIdx.x;   // 0..B*64-1
    int b = i >> 6, d = i & 63;
    float x = X[i];
    g_Xcat[b * KDIM + d]        = x * x;
    g_Xcat[b * KDIM + D_SZ + d] = x;
}

// ---------------- kernel 3: phase A GEMM + exp -> W ----------------
// grid (8 mblocks, 16 bblocks), 256 threads. Tile 128x128, K=128 in 8 steps of 16.
__global__ __launch_bounds__(256) void phaseA() {
    __shared__ float As[16][132];   // [k][row] (padded)
    __shared__ float Bs[16][128];   // [k][col]

    int tx = threadIdx.x;
    int tr = tx >> 4;               // 0..15 -> row group
    int tc = tx & 15;               // 0..15 -> col group
    int brow0 = blockIdx.y * 128;
    int mcol0 = blockIdx.x * 128;

    float acc[8][8];
    #pragma unroll
    for (int i = 0; i < 8; i++)
        #pragma unroll
        for (int j = 0; j < 8; j++) acc[i][j] = 0.0f;

    for (int k0 = 0; k0 < KDIM; k0 += 16) {
        // load A tile transposed: 128 rows x 16 k
        #pragma unroll
        for (int i = 0; i < 2; i++) {
            int idx = tx + i * 256;          // 0..511
            int row = idx >> 2;
            int kq  = idx & 3;
            const float4 v = *(const float4*)&g_Xcat[(brow0 + row) * KDIM + k0 + kq * 4];
            As[kq * 4 + 0][row] = v.x;
            As[kq * 4 + 1][row] = v.y;
            As[kq * 4 + 2][row] = v.z;
            As[kq * 4 + 3][row] = v.w;
        }
        // load B tile: 16 k x 128 m
        #pragma unroll
        for (int i = 0; i < 2; i++) {
            int idx = tx + i * 256;
            int kk = idx >> 5;
            int mq = idx & 31;
            *(float4*)&Bs[kk][mq * 4] =
                *(const float4*)&g_Bmat[(k0 + kk) * M_SZ + mcol0 + mq * 4];
        }
        __syncthreads();
        #pragma unroll
        for (int k = 0; k < 16; k++) {
            float a[8], bb[8];
            *(float4*)&a[0]  = *(const float4*)&As[k][tr * 8];
            *(float4*)&a[4]  = *(const float4*)&As[k][tr * 8 + 4];
            *(float4*)&bb[0] = *(const float4*)&Bs[k][tc * 8];
            *(float4*)&bb[4] = *(const float4*)&Bs[k][tc * 8 + 4];
            #pragma unroll
            for (int i = 0; i < 8; i++)
                #pragma unroll
                for (int j = 0; j < 8; j++)
                    acc[i][j] = fmaf(a[i], bb[j], acc[i][j]);
        }
        __syncthreads();
    }

    // epilogue: logw = -0.5*S + hb ; clip ; W = exp(logw)*Lam
    float2 hl[8];
    #pragma unroll
    for (int j = 0; j < 8; j++) hl[j] = g_hl[mcol0 + tc * 8 + j];

    #pragma unroll
    for (int i = 0; i < 8; i++) {
        float w[8];
        #pragma unroll
        for (int j = 0; j < 8; j++) {
            float lw = fmaf(acc[i][j], -0.5f, hl[j].x);
            lw = fminf(fmaxf(lw, -50.0f), 50.0f);
            w[j] = __expf(lw) * hl[j].y;
        }
        float* dst = &g_W[(brow0 + tr * 8 + i) * M_SZ + mcol0 + tc * 8];
        *(float4*)&dst[0] = make_float4(w[0], w[1], w[2], w[3]);
        *(float4*)&dst[4] = make_float4(w[4], w[5], w[6], w[7]);
    }
}

// ---------------- kernel 4: phase B split-M GEMM -> partial T1,T2,norm ----------------
// grid (8 mchunks, 16 bblocks), 256 threads. Each block: 128 rows x 128 cols, 128 m's.
__global__ __launch_bounds__(256) void phaseB() {
    __shared__ float Ws[32][132];   // [m][row] (padded)
    __shared__ float Ps[32][128];   // [m][col]

    int tx = threadIdx.x;
    int tr = tx >> 4;               // row group
    int tc = tx & 15;               // col group (4 T1 cols + 4 T2 cols)
    int brow0 = blockIdx.y * 128;
    int chunk = blockIdx.x;
    int m0 = chunk * 128;

    float acc[8][8];
    #pragma unroll
    for (int i = 0; i < 8; i++)
        #pragma unroll
        for (int j = 0; j < 8; j++) acc[i][j] = 0.0f;
    float nrm = 0.0f;

    for (int mt = 0; mt < 128; mt += 32) {
        // load W tile transposed: 128 rows x 32 m -> Ws[m][row]
        #pragma unroll
        for (int i = 0; i < 4; i++) {
            int idx = tx + i * 256;          // 0..1023
            int row = idx >> 3;
            int mq  = idx & 7;
            const float4 v = *(const float4*)&g_W[(brow0 + row) * M_SZ + m0 + mt + mq * 4];
            Ws[mq * 4 + 0][row] = v.x;
            Ws[mq * 4 + 1][row] = v.y;
            Ws[mq * 4 + 2][row] = v.z;
            Ws[mq * 4 + 3][row] = v.w;
        }
        // load P tile: 32 m x 128 k
        #pragma unroll
        for (int i = 0; i < 4; i++) {
            int idx = tx + i * 256;
            int mm = idx >> 5;
            int cq = idx & 31;
            *(float4*)&Ps[mm][cq * 4] =
                *(const float4*)&g_P[(m0 + mt + mm) * KDIM + cq * 4];
        }
        __syncthreads();

        // norm partial: threads 0..127 each own one row
        if (tx < 128) {
            #pragma unroll
            for (int mm = 0; mm < 32; mm++) nrm += Ws[mm][tx];
        }

        #pragma unroll
        for (int mm = 0; mm < 32; mm++) {
            float a[8], bb[8];
            *(float4*)&a[0]  = *(const float4*)&Ws[mm][tr * 8];
            *(float4*)&a[4]  = *(const float4*)&Ws[mm][tr * 8 + 4];
            *(float4*)&bb[0] = *(const float4*)&Ps[mm][tc * 4];          // K part
            *(float4*)&bb[4] = *(const float4*)&Ps[mm][D_SZ + tc * 4];   // c part
            #pragma unroll
            for (int i = 0; i < 8; i++)
                #pragma unroll
                for (int j = 0; j < 8; j++)
                    acc[i][j] = fmaf(a[i], bb[j], acc[i][j]);
        }
        __syncthreads();
    }

    // store partials
    #pragma unroll
    for (int i = 0; i < 8; i++) {
        int row = brow0 + tr * 8 + i;
        float* dst = &g_Tpart[(size_t)chunk * (B_SZ * KDIM) + row * KDIM];
        *(float4*)&dst[tc * 4]        = make_float4(acc[i][0], acc[i][1], acc[i][2], acc[i][3]);
        *(float4*)&dst[D_SZ + tc * 4] = make_float4(acc[i][4], acc[i][5], acc[i][6], acc[i][7]);
    }
    if (tx < 128) g_npart[chunk * B_SZ + brow0 + tx] = nrm;
}

// ---------------- kernel 5: finalize ----------------
__global__ void finalize(const float* __restrict__ X, float* __restrict__ out) {
    int i = blockIdx.x * blockDim.x + threadIdx.x;   // 0..B*64-1
    int b = i >> 6, d = i & 63;
    float t1 = 0.0f, t2 = 0.0f, nr = 0.0f;
    #pragma unroll
    for (int ch = 0; ch < 8; ch++) {
        t1 += g_Tpart[(size_t)ch * (B_SZ * KDIM) + b * KDIM + d];
        t2 += g_Tpart[(size_t)ch * (B_SZ * KDIM) + b * KDIM + D_SZ + d];
        nr += g_npart[ch * B_SZ + b];
    }
    out[i] = (X[i] * t1 + t2) / nr;
}

// ---------------- launch ----------------
extern "C" void kernel_launch(void* const* d_in, const int* in_sizes, int n_in,
                              void* d_out, int out_size) {
    const float* X   = (const float*)d_in[0];
    const float* Mu0 = (const float*)d_in[1];
    const float* Mu1 = (const float*)d_in[2];
    const float* S0  = (const float*)d_in[3];
    const float* S1  = (const float*)d_in[4];
    const float* Lam = (const float*)d_in[5];
    const float* tp  = (const float*)d_in[6];
    const float* ep  = (const float*)d_in[7];
    float* out = (float*)d_out;

    precompute_params<<<M_SZ, 64>>>(Mu0, Mu1, S0, S1, Lam, tp, ep);
    precompute_x<<<(B_SZ * D_SZ) / 256, 256>>>(X);
    phaseA<<<dim3(M_SZ / 128, B_SZ / 128), 256>>>();
    phaseB<<<dim3(8, B_SZ / 128), 256>>>();
    finalize<<<(B_SZ * D_SZ) / 256, 256>>>(X, out);
}

// round 2
// speedup vs baseline: 1.0900x; 1.0900x over previous
#include <cuda_runtime.h>
#include <math.h>

#define B_SZ 2048
#define M_SZ 1024
#define D_SZ 64
#define KDIM 128   // 2*D_SZ

typedef unsigned long long ull;

// ---------------- device scratch (no allocations allowed) ----------------
__device__ float  g_Xcat[B_SZ * KDIM];          // [b][k] : k<64 -> x^2, k>=64 -> x
__device__ float  g_Bmat[KDIM * M_SZ];          // [k][m] : k<64 -> 1/Sigma, k>=64 -> -2*mut/Sigma
__device__ float2 g_hl[M_SZ];                   // (.x = -0.5*sum(mut^2/Sig + log Sig), .y = Lam)
__device__ float  g_P[M_SZ * KDIM];             // [m][k] : k<64 -> K, k>=64 -> c = v - K*mut
__device__ float  g_W[B_SZ * M_SZ];             // weights
__device__ float  g_Tpart[8 * B_SZ * KDIM];     // per-mchunk partial [T1|T2]
__device__ float  g_npart[8 * B_SZ];            // per-mchunk partial norm

// ---------------- f32x2 packed FMA helpers ----------------
__device__ __forceinline__ void ffma2(ull& d, ull a, ull b) {
    asm("fma.rn.f32x2 %0, %1, %2, %0;" : "+l"(d) : "l"(a), "l"(b));
}
__device__ __forceinline__ ull splat2(float x) {
    ull r;
    asm("mov.b64 %0, {%1, %1};" : "=l"(r) : "f"(x));
    return r;
}
__device__ __forceinline__ void unpack2(ull v, float& lo, float& hi) {
    asm("mov.b64 {%0, %1}, %2;" : "=f"(lo), "=f"(hi) : "l"(v));
}
union F4U { float4 f; ull u[2]; };

// ---------------- kernel 1: per-component parameter precompute ----------------
__global__ void precompute_params(const float* __restrict__ Mu0,
                                  const float* __restrict__ Mu1,
                                  const float* __restrict__ S0,
                                  const float* __restrict__ S1,
                                  const float* __restrict__ Lam,
                                  const float* __restrict__ tp,
                                  const float* __restrict__ ep) {
    int m = blockIdx.x;
    int d = threadIdx.x;      // 64 threads
    float t   = tp[0];
    float eps = ep[0];
    float eps2 = eps * eps;
    float eps4 = eps2 * eps2;
    float omt  = 1.0f - t;

    int id = m * D_SZ + d;
    float s0  = S0[id], s1 = S1[id];
    float mu0 = Mu0[id], mu1 = Mu1[id];

    float Ds = sqrtf(4.0f * s0 * s1 + eps4);
    float Cs = 0.5f * (Ds - eps2);
    float mt = omt * mu0 + t * mu1;
    float Sg = omt * omt * s0 + t * t * s1 + 2.0f * t * omt * (Cs + 0.5f * eps2);
    float Pt = t * s1 + omt * Cs;
    float Qt = omt * s0 + t * Cs;
    float St = Pt - Qt - eps2 * t;
    float inv = 1.0f / Sg;
    float Kk  = St * inv;
    float v   = mu1 - mu0;
    float c   = v - Kk * mt;

    g_Bmat[d * M_SZ + m]           = inv;
    g_Bmat[(D_SZ + d) * M_SZ + m]  = -2.0f * mt * inv;
    g_P[m * KDIM + d]              = Kk;
    g_P[m * KDIM + D_SZ + d]       = c;

    // reduce h = sum_d (mut^2*inv + log Sigma)
    __shared__ float red[64];
    red[d] = mt * mt * inv + logf(Sg);
    __syncthreads();
    #pragma unroll
    for (int s = 32; s > 0; s >>= 1) {
        if (d < s) red[d] += red[d + s];
        __syncthreads();
    }
    if (d == 0) g_hl[m] = make_float2(-0.5f * red[0], Lam[m]);
}

// ---------------- kernel 2: build Xcat ----------------
__global__ void precompute_x(const float* __restrict__ X) {
    int i = blockIdx.x * blockDim.x + threadIdx.x;   // 0..B*64-1
    int b = i >> 6, d = i & 63;
    float x = X[i];
    g_Xcat[b * KDIM + d]        = x * x;
    g_Xcat[b * KDIM + D_SZ + d] = x;
}

// ---------------- kernel 3: phase A GEMM + exp -> W ----------------
// grid (8 mblocks, 16 bblocks), 256 threads. Tile 128x128, K=128 in 8 steps of 16.
// Accumulators packed f32x2 along the row (i) dimension: acc2[ip][j] = (acc[2ip][j], acc[2ip+1][j]).
__global__ __launch_bounds__(256) void phaseA() {
    __shared__ float As[16][132];   // [k][row] (padded)
    __shared__ float Bs[16][128];   // [k][col]

    int tx = threadIdx.x;
    int tr = tx >> 4;               // 0..15 -> row group
    int tc = tx & 15;               // 0..15 -> col group
    int brow0 = blockIdx.y * 128;
    int mcol0 = blockIdx.x * 128;

    ull acc2[4][8];
    #pragma unroll
    for (int i = 0; i < 4; i++)
        #pragma unroll
        for (int j = 0; j < 8; j++) acc2[i][j] = 0ULL;

    for (int k0 = 0; k0 < KDIM; k0 += 16) {
        // load A tile transposed: 128 rows x 16 k
        #pragma unroll
        for (int i = 0; i < 2; i++) {
            int idx = tx + i * 256;          // 0..511
            int row = idx >> 2;
            int kq  = idx & 3;
            const float4 v = *(const float4*)&g_Xcat[(brow0 + row) * KDIM + k0 + kq * 4];
            As[kq * 4 + 0][row] = v.x;
            As[kq * 4 + 1][row] = v.y;
            As[kq * 4 + 2][row] = v.z;
            As[kq * 4 + 3][row] = v.w;
        }
        // load B tile: 16 k x 128 m
        #pragma unroll
        for (int i = 0; i < 2; i++) {
            int idx = tx + i * 256;
            int kk = idx >> 5;
            int mq = idx & 31;
            *(float4*)&Bs[kk][mq * 4] =
                *(const float4*)&g_Bmat[(k0 + kk) * M_SZ + mcol0 + mq * 4];
        }
        __syncthreads();
        #pragma unroll
        for (int k = 0; k < 16; k++) {
            F4U a0, a1, b0, b1;
            a0.f = *(const float4*)&As[k][tr * 8];
            a1.f = *(const float4*)&As[k][tr * 8 + 4];
            b0.f = *(const float4*)&Bs[k][tc * 8];
            b1.f = *(const float4*)&Bs[k][tc * 8 + 4];
            ull ap[4] = { a0.u[0], a0.u[1], a1.u[0], a1.u[1] };
            ull bs[8];
            bs[0] = splat2(b0.f.x); bs[1] = splat2(b0.f.y);
            bs[2] = splat2(b0.f.z); bs[3] = splat2(b0.f.w);
            bs[4] = splat2(b1.f.x); bs[5] = splat2(b1.f.y);
            bs[6] = splat2(b1.f.z); bs[7] = splat2(b1.f.w);
            #pragma unroll
            for (int i = 0; i < 4; i++)
                #pragma unroll
                for (int j = 0; j < 8; j++)
                    ffma2(acc2[i][j], ap[i], bs[j]);
        }
        __syncthreads();
    }

    // unpack accumulators
    float acc[8][8];
    #pragma unroll
    for (int i = 0; i < 4; i++)
        #pragma unroll
        for (int j = 0; j < 8; j++)
            unpack2(acc2[i][j], acc[2 * i][j], acc[2 * i + 1][j]);

    // epilogue: logw = -0.5*S + hb ; clip ; W = exp(logw)*Lam
    float2 hl[8];
    #pragma unroll
    for (int j = 0; j < 8; j++) hl[j] = g_hl[mcol0 + tc * 8 + j];

    #pragma unroll
    for (int i = 0; i < 8; i++) {
        float w[8];
        #pragma unroll
        for (int j = 0; j < 8; j++) {
            float lw = fmaf(acc[i][j], -0.5f, hl[j].x);
            lw = fminf(fmaxf(lw, -50.0f), 50.0f);
            w[j] = __expf(lw) * hl[j].y;
        }
        float* dst = &g_W[(brow0 + tr * 8 + i) * M_SZ + mcol0 + tc * 8];
        *(float4*)&dst[0] = make_float4(w[0], w[1], w[2], w[3]);
        *(float4*)&dst[4] = make_float4(w[4], w[5], w[6], w[7]);
    }
}

// ---------------- kernel 4: phase B split-M GEMM -> partial T1,T2,norm ----------------
// grid (8 mchunks, 16 bblocks), 256 threads. Each block: 128 rows x 128 cols, 128 m's.
__global__ __launch_bounds__(256) void phaseB() {
    __shared__ float Ws[32][132];   // [m][row] (padded)
    __shared__ float Ps[32][128];   // [m][col]

    int tx = threadIdx.x;
    int tr = tx >> 4;               // row group
    int tc = tx & 15;               // col group (4 T1 cols + 4 T2 cols)
    int brow0 = blockIdx.y * 128;
    int chunk = blockIdx.x;
    int m0 = chunk * 128;

    ull acc2[4][8];
    #pragma unroll
    for (int i = 0; i < 4; i++)
        #pragma unroll
        for (int j = 0; j < 8; j++) acc2[i][j] = 0ULL;
    float nrm = 0.0f;

    for (int mt = 0; mt < 128; mt += 32) {
        // load W tile transposed: 128 rows x 32 m -> Ws[m][row]
        #pragma unroll
        for (int i = 0; i < 4; i++) {
            int idx = tx + i * 256;          // 0..1023
            int row = idx >> 3;
            int mq  = idx & 7;
            const float4 v = *(const float4*)&g_W[(brow0 + row) * M_SZ + m0 + mt + mq * 4];
            Ws[mq * 4 + 0][row] = v.x;
            Ws[mq * 4 + 1][row] = v.y;
            Ws[mq * 4 + 2][row] = v.z;
            Ws[mq * 4 + 3][row] = v.w;
        }
        // load P tile: 32 m x 128 k
        #pragma unroll
        for (int i = 0; i < 4; i++) {
            int idx = tx + i * 256;
            int mm = idx >> 5;
            int cq = idx & 31;
            *(float4*)&Ps[mm][cq * 4] =
                *(const float4*)&g_P[(m0 + mt + mm) * KDIM + cq * 4];
        }
        __syncthreads();

        // norm partial: threads 0..127 each own one row
        if (tx < 128) {
            #pragma unroll
            for (int mm = 0; mm < 32; mm++) nrm += Ws[mm][tx];
        }

        #pragma unroll
        for (int mm = 0; mm < 32; mm++) {
            F4U a0, a1, b0, b1;
            a0.f = *(const float4*)&Ws[mm][tr * 8];
            a1.f = *(const float4*)&Ws[mm][tr * 8 + 4];
            b0.f = *(const float4*)&Ps[mm][tc * 4];          // K part
            b1.f = *(const float4*)&Ps[mm][D_SZ + tc * 4];   // c part
            ull ap[4] = { a0.u[0], a0.u[1], a1.u[0], a1.u[1] };
            ull bs[8];
            bs[0] = splat2(b0.f.x); bs[1] = splat2(b0.f.y);
            bs[2] = splat2(b0.f.z); bs[3] = splat2(b0.f.w);
            bs[4] = splat2(b1.f.x); bs[5] = splat2(b1.f.y);
            bs[6] = splat2(b1.f.z); bs[7] = splat2(b1.f.w);
            #pragma unroll
            for (int i = 0; i < 4; i++)
                #pragma unroll
                for (int j = 0; j < 8; j++)
                    ffma2(acc2[i][j], ap[i], bs[j]);
        }
        __syncthreads();
    }

    // unpack accumulators
    float acc[8][8];
    #pragma unroll
    for (int i = 0; i < 4; i++)
        #pragma unroll
        for (int j = 0; j < 8; j++)
            unpack2(acc2[i][j], acc[2 * i][j], acc[2 * i + 1][j]);

    // store partials
    #pragma unroll
    for (int i = 0; i < 8; i++) {
        int row = brow0 + tr * 8 + i;
        float* dst = &g_Tpart[(size_t)chunk * (B_SZ * KDIM) + row * KDIM];
        *(float4*)&dst[tc * 4]        = make_float4(acc[i][0], acc[i][1], acc[i][2], acc[i][3]);
        *(float4*)&dst[D_SZ + tc * 4] = make_float4(acc[i][4], acc[i][5], acc[i][6], acc[i][7]);
    }
    if (tx < 128) g_npart[chunk * B_SZ + brow0 + tx] = nrm;
}

// ---------------- kernel 5: finalize ----------------
__global__ void finalize(const float* __restrict__ X, float* __restrict__ out) {
    int i = blockIdx.x * blockDim.x + threadIdx.x;   // 0..B*64-1
    int b = i >> 6, d = i & 63;
    float t1 = 0.0f, t2 = 0.0f, nr = 0.0f;
    #pragma unroll
    for (int ch = 0; ch < 8; ch++) {
        t1 += g_Tpart[(size_t)ch * (B_SZ * KDIM) + b * KDIM + d];
        t2 += g_Tpart[(size_t)ch * (B_SZ * KDIM) + b * KDIM + D_SZ + d];
        nr += g_npart[ch * B_SZ + b];
    }
    out[i] = (X[i] * t1 + t2) / nr;
}

// ---------------- launch ----------------
extern "C" void kernel_launch(void* const* d_in, const int* in_sizes, int n_in,
                              void* d_out, int out_size) {
    const float* X   = (const float*)d_in[0];
    const float* Mu0 = (const float*)d_in[1];
    const float* Mu1 = (const float*)d_in[2];
    const float* S0  = (const float*)d_in[3];
    const float* S1  = (const float*)d_in[4];
    const float* Lam = (const float*)d_in[5];
    const float* tp  = (const float*)d_in[6];
    const float* ep  = (const float*)d_in[7];
    float* out = (float*)d_out;

    precompute_params<<<M_SZ, 64>>>(Mu0, Mu1, S0, S1, Lam, tp, ep);
    precompute_x<<<(B_SZ * D_SZ) / 256, 256>>>(X);
    phaseA<<<dim3(M_SZ / 128, B_SZ / 128), 256>>>();
    phaseB<<<dim3(8, B_SZ / 128), 256>>>();
    finalize<<<(B_SZ * D_SZ) / 256, 256>>>(X, out);
}